// round 2
// baseline (speedup 1.0000x reference)
#include <cuda_runtime.h>
#include <cuda_fp16.h>
#include <mma.h>
#include <cstdint>
#include <cstddef>

using namespace nvcuda;

#define Bz 16
#define Sz 512
#define Hz 768
#define Lz 12
#define NHz 12
#define Iz 3072
#define DHz 64

// ---------------- scratch (device globals; no allocations allowed) ----------
__device__ float  g_x[Bz*Sz*Hz];        // fp32 master activation
__device__ float  g_tmp[Bz*Sz*Hz];      // pre-LN buffer
__device__ float  g_attn[Bz*Sz*Hz];     // attn_out fp32 (FFN residual)
__device__ __half g_xb[Bz*Sz*Hz];
__device__ __half g_attnb[Bz*Sz*Hz];
__device__ __half g_q[Bz*Sz*Hz];
__device__ __half g_k[Bz*Sz*Hz];
__device__ __half g_v[Bz*Sz*Hz];
__device__ __half g_ctx[Bz*Sz*Hz];
__device__ __half g_h[Bz*Sz*Iz];
__device__ float  g_scores[(size_t)Bz*NHz*Sz*Sz];
__device__ __half g_probs[(size_t)Bz*NHz*Sz*Sz];
__device__ __half g_wq[Lz*Hz*Hz];
__device__ __half g_wk[Lz*Hz*Hz];
__device__ __half g_wv[Lz*Hz*Hz];
__device__ __half g_wo[Lz*Hz*Hz];
__device__ __half g_wi[(size_t)Lz*Hz*Iz];
__device__ __half g_wo2[(size_t)Lz*Hz*Iz];

// ---------------- fp32 -> fp16 conversion ----------------------------------
__global__ void f2h_k(const float* __restrict__ s, __half* __restrict__ d, int n4) {
    int i = blockIdx.x * 256 + threadIdx.x;
    if (i < n4) {
        float4 f = ((const float4*)s)[i];
        __half2* dp = (__half2*)d;
        dp[2*i]   = __floats2half2_rn(f.x, f.y);
        dp[2*i+1] = __floats2half2_rn(f.z, f.w);
    }
}

// ---------------- block reductions ------------------------------------------
__device__ __forceinline__ float bsum256(float v, float* sm) {
    #pragma unroll
    for (int o = 16; o; o >>= 1) v += __shfl_xor_sync(0xFFFFFFFFu, v, o);
    int t = threadIdx.x;
    if ((t & 31) == 0) sm[t >> 5] = v;
    __syncthreads();
    float r = sm[0];
    #pragma unroll
    for (int i = 1; i < 8; i++) r += sm[i];
    __syncthreads();
    return r;
}

// ---------------- embedding + LN (row per block, 256 thr) ------------------
__global__ void embed_ln_k(const int* __restrict__ ids,
                           const float* __restrict__ we,
                           const float* __restrict__ pe,
                           const float* __restrict__ te,
                           const float* __restrict__ g,
                           const float* __restrict__ b,
                           float* __restrict__ dF,
                           __half* __restrict__ dB) {
    __shared__ float sm[8];
    int row = blockIdx.x;
    int s_ = row & (Sz - 1);
    int id = ids[row];
    int t = threadIdx.x;
    float v[3];
    #pragma unroll
    for (int i = 0; i < 3; i++) {
        int col = t + i * 256;
        v[i] = we[(size_t)id * Hz + col] + pe[(size_t)(s_ + 2) * Hz + col] + te[col];
    }
    float mean = bsum256(v[0] + v[1] + v[2], sm) * (1.0f / Hz);
    float d0 = v[0] - mean, d1 = v[1] - mean, d2 = v[2] - mean;
    float var = bsum256(d0*d0 + d1*d1 + d2*d2, sm) * (1.0f / Hz);
    float rs = rsqrtf(var + 1e-5f);
    size_t base = (size_t)row * Hz;
    #pragma unroll
    for (int i = 0; i < 3; i++) {
        int col = t + i * 256;
        float y = (v[i] - mean) * rs * g[col] + b[col];
        dF[base + col] = y;
        dB[base + col] = __float2half_rn(y);
    }
}

// ---------------- LayerNorm (row per block) ---------------------------------
__global__ void ln_k(const float* __restrict__ src,
                     const float* __restrict__ g,
                     const float* __restrict__ b,
                     float* __restrict__ dF,
                     __half* __restrict__ dB) {
    __shared__ float sm[8];
    size_t base = (size_t)blockIdx.x * Hz;
    int t = threadIdx.x;
    float v[3];
    #pragma unroll
    for (int i = 0; i < 3; i++) v[i] = src[base + t + i * 256];
    float mean = bsum256(v[0] + v[1] + v[2], sm) * (1.0f / Hz);
    float d0 = v[0] - mean, d1 = v[1] - mean, d2 = v[2] - mean;
    float var = bsum256(d0*d0 + d1*d1 + d2*d2, sm) * (1.0f / Hz);
    float rs = rsqrtf(var + 1e-5f);
    #pragma unroll
    for (int i = 0; i < 3; i++) {
        int col = t + i * 256;
        float y = (v[i] - mean) * rs * g[col] + b[col];
        if (dF) dF[base + col] = y;
        dB[base + col] = __float2half_rn(y);
    }
}

// ---------------- softmax over 512 (row per block, 128 thr) -----------------
__global__ void softmax_k(const float* __restrict__ s, __half* __restrict__ p) {
    __shared__ float sm[4];
    size_t base = (size_t)blockIdx.x * Sz;
    int t = threadIdx.x;
    float v0 = s[base + t], v1 = s[base + t + 128], v2 = s[base + t + 256], v3 = s[base + t + 384];
    float m = fmaxf(fmaxf(v0, v1), fmaxf(v2, v3));
    #pragma unroll
    for (int o = 16; o; o >>= 1) m = fmaxf(m, __shfl_xor_sync(0xFFFFFFFFu, m, o));
    if ((t & 31) == 0) sm[t >> 5] = m;
    __syncthreads();
    float mm = fmaxf(fmaxf(sm[0], sm[1]), fmaxf(sm[2], sm[3]));
    __syncthreads();
    float e0 = __expf(v0 - mm), e1 = __expf(v1 - mm), e2 = __expf(v2 - mm), e3 = __expf(v3 - mm);
    float su = e0 + e1 + e2 + e3;
    #pragma unroll
    for (int o = 16; o; o >>= 1) su += __shfl_xor_sync(0xFFFFFFFFu, su, o);
    if ((t & 31) == 0) sm[t >> 5] = su;
    __syncthreads();
    float inv = 1.0f / (sm[0] + sm[1] + sm[2] + sm[3]);
    p[base + t]       = __float2half_rn(e0 * inv);
    p[base + t + 128] = __float2half_rn(e1 * inv);
    p[base + t + 256] = __float2half_rn(e2 * inv);
    p[base + t + 384] = __float2half_rn(e3 * inv);
}

// ---------------- generic batched fp16 GEMM (wmma) ---------------------------
// Tile: BM=128 BN=64 BK=32, 256 threads (8 warps, 4x2), warp tile 32x32.
// EPI: 0 outB = acc (+bias)        1 outF = acc + bias + residual
//      2 outB = gelu(acc + bias)   3 outF = acc * alpha
// BT:  false -> B row-major [K,N]; true -> B is N-major source (col_major frag, QK^T).
struct GP {
    const __half* A;
    const __half* Bm;
    const float* bias;
    const float* res;
    float* outF;
    __half* outB;
    int M, N, K, lda, ldb, ldr, ldo, zdiv;
    long long sAo, sAi, sBo, sBi, sRo, sRi, sOo, sOi;
    float alpha;
};

template<int EPI, bool BT>
__global__ void __launch_bounds__(256) gemm_k(GP p) {
    __shared__ alignas(16) unsigned char smraw[34816];
    __half* sa = (__half*)smraw;             // 128 x 48
    __half* sb = (__half*)(smraw + 12288);   // 32x80 (row) / 64x40 (col)
    float* ep = (float*)smraw;               // 128 x 68 fp32 (reuse)

    int z = blockIdx.z;
    int zo = z / p.zdiv, zi = z - zo * p.zdiv;
    const __half* A  = p.A  + zo * p.sAo + zi * p.sAi;
    const __half* Bm = p.Bm + zo * p.sBo + zi * p.sBi;
    const float* res = p.res ? p.res + zo * p.sRo + zi * p.sRi : nullptr;
    float* outF = p.outF ? p.outF + zo * p.sOo + zi * p.sOi : nullptr;
    __half* outB = p.outB ? p.outB + zo * p.sOo + zi * p.sOi : nullptr;

    const int m0 = blockIdx.y * 128, n0 = blockIdx.x * 64;
    const int tid = threadIdx.x;
    const int wid = tid >> 5, wm = wid >> 1, wn = wid & 1;

    wmma::fragment<wmma::accumulator, 16, 16, 16, float> acc[2][2];
    #pragma unroll
    for (int i = 0; i < 2; i++)
        #pragma unroll
        for (int j = 0; j < 2; j++) wmma::fill_fragment(acc[i][j], 0.0f);

    for (int k0 = 0; k0 < p.K; k0 += 32) {
        __syncthreads();
        // load A tile 128x32
        #pragma unroll
        for (int c = tid; c < 512; c += 256) {
            int r = c >> 2, col = (c & 3) << 3;
            *(uint4*)(sa + r * 48 + col) =
                *(const uint4*)(A + (size_t)(m0 + r) * p.lda + k0 + col);
        }
        // load B tile
        if (!BT) {
            int r = tid >> 3, col = (tid & 7) << 3;
            *(uint4*)(sb + r * 80 + col) =
                *(const uint4*)(Bm + (size_t)(k0 + r) * p.ldb + n0 + col);
        } else {
            int col = tid >> 2, d = (tid & 3) << 3;
            *(uint4*)(sb + col * 40 + d) =
                *(const uint4*)(Bm + (size_t)(n0 + col) * p.ldb + k0 + d);
        }
        __syncthreads();
        #pragma unroll
        for (int kk = 0; kk < 2; kk++) {
            wmma::fragment<wmma::matrix_a, 16, 16, 16, __half, wmma::row_major> af[2];
            #pragma unroll
            for (int i = 0; i < 2; i++)
                wmma::load_matrix_sync(af[i], sa + (wm * 32 + i * 16) * 48 + kk * 16, 48);
            if constexpr (!BT) {
                wmma::fragment<wmma::matrix_b, 16, 16, 16, __half, wmma::row_major> bf[2];
                #pragma unroll
                for (int j = 0; j < 2; j++)
                    wmma::load_matrix_sync(bf[j], sb + (kk * 16) * 80 + wn * 32 + j * 16, 80);
                #pragma unroll
                for (int i = 0; i < 2; i++)
                    #pragma unroll
                    for (int j = 0; j < 2; j++)
                        wmma::mma_sync(acc[i][j], af[i], bf[j], acc[i][j]);
            } else {
                wmma::fragment<wmma::matrix_b, 16, 16, 16, __half, wmma::col_major> bf[2];
                #pragma unroll
                for (int j = 0; j < 2; j++)
                    wmma::load_matrix_sync(bf[j], sb + (wn * 32 + j * 16) * 40 + kk * 16, 40);
                #pragma unroll
                for (int i = 0; i < 2; i++)
                    #pragma unroll
                    for (int j = 0; j < 2; j++)
                        wmma::mma_sync(acc[i][j], af[i], bf[j], acc[i][j]);
            }
        }
    }
    __syncthreads();
    #pragma unroll
    for (int i = 0; i < 2; i++)
        #pragma unroll
        for (int j = 0; j < 2; j++)
            wmma::store_matrix_sync(ep + (wm * 32 + i * 16) * 68 + wn * 32 + j * 16,
                                    acc[i][j], 68, wmma::mem_row_major);
    __syncthreads();

    for (int e = tid; e < 128 * 64; e += 256) {
        int r = e >> 6, cc = e & 63;
        float v = ep[r * 68 + cc];
        int gm = m0 + r, gn = n0 + cc;
        if (EPI == 0) {
            if (p.bias) v += p.bias[gn];
            outB[(size_t)gm * p.ldo + gn] = __float2half_rn(v);
        } else if (EPI == 1) {
            v += p.bias[gn] + res[(size_t)gm * p.ldr + gn];
            outF[(size_t)gm * p.ldo + gn] = v;
        } else if (EPI == 2) {
            v += p.bias[gn];
            v = 0.5f * v * (1.0f + erff(v * 0.70710678118654752f));
            outB[(size_t)gm * p.ldo + gn] = __float2half_rn(v);
        } else { // 3
            outF[(size_t)gm * p.ldo + gn] = v * p.alpha;
        }
    }
}

// ---------------- host orchestration ----------------------------------------
extern "C" void kernel_launch(void* const* d_in, const int* in_sizes, int n_in,
                              void* d_out, int out_size) {
    const int*   ids   = (const int*)d_in[0];
    const float* word  = (const float*)d_in[1];
    const float* pos   = (const float*)d_in[2];
    const float* type0 = (const float*)d_in[3];
    const float* lneg  = (const float*)d_in[4];
    const float* lneb  = (const float*)d_in[5];
    const float* Wq    = (const float*)d_in[6];
    const float* bq    = (const float*)d_in[7];
    const float* Wk    = (const float*)d_in[8];
    const float* bk    = (const float*)d_in[9];
    const float* Wv    = (const float*)d_in[10];
    const float* bv    = (const float*)d_in[11];
    const float* Wo    = (const float*)d_in[12];
    const float* bo    = (const float*)d_in[13];
    const float* ln1g  = (const float*)d_in[14];
    const float* ln1b  = (const float*)d_in[15];
    const float* Wi    = (const float*)d_in[16];
    const float* bi    = (const float*)d_in[17];
    const float* Wo2   = (const float*)d_in[18];
    const float* bo2   = (const float*)d_in[19];
    const float* ln2g  = (const float*)d_in[20];
    const float* ln2b  = (const float*)d_in[21];

    float *x, *tmp, *attn, *scores;
    __half *xb, *attnb, *q_, *k_, *v_, *ctx, *hh, *probs, *wq, *wk, *wv, *wo, *wi, *wo2;
    cudaGetSymbolAddress((void**)&x,     g_x);
    cudaGetSymbolAddress((void**)&tmp,   g_tmp);
    cudaGetSymbolAddress((void**)&attn,  g_attn);
    cudaGetSymbolAddress((void**)&scores,g_scores);
    cudaGetSymbolAddress((void**)&xb,    g_xb);
    cudaGetSymbolAddress((void**)&attnb, g_attnb);
    cudaGetSymbolAddress((void**)&q_,    g_q);
    cudaGetSymbolAddress((void**)&k_,    g_k);
    cudaGetSymbolAddress((void**)&v_,    g_v);
    cudaGetSymbolAddress((void**)&ctx,   g_ctx);
    cudaGetSymbolAddress((void**)&hh,    g_h);
    cudaGetSymbolAddress((void**)&probs, g_probs);
    cudaGetSymbolAddress((void**)&wq,    g_wq);
    cudaGetSymbolAddress((void**)&wk,    g_wk);
    cudaGetSymbolAddress((void**)&wv,    g_wv);
    cudaGetSymbolAddress((void**)&wo,    g_wo);
    cudaGetSymbolAddress((void**)&wi,    g_wi);
    cudaGetSymbolAddress((void**)&wo2,   g_wo2);

    // weight fp32 -> fp16
    auto conv = [&](const float* src, __half* dst, size_t n) {
        int n4 = (int)(n / 4);
        f2h_k<<<(n4 + 255) / 256, 256>>>(src, dst, n4);
    };
    conv(Wq,  wq,  (size_t)Lz * Hz * Hz);
    conv(Wk,  wk,  (size_t)Lz * Hz * Hz);
    conv(Wv,  wv,  (size_t)Lz * Hz * Hz);
    conv(Wo,  wo,  (size_t)Lz * Hz * Hz);
    conv(Wi,  wi,  (size_t)Lz * Hz * Iz);
    conv(Wo2, wo2, (size_t)Lz * Hz * Iz);

    // embeddings + LN_e
    embed_ln_k<<<Bz * Sz, 256>>>(ids, word, pos, type0, lneg, lneb, x, xb);

    const int M = Bz * Sz; // 8192
    for (int l = 0; l < Lz; l++) {
        const __half* wql  = wq  + (size_t)l * Hz * Hz;
        const __half* wkl  = wk  + (size_t)l * Hz * Hz;
        const __half* wvl  = wv  + (size_t)l * Hz * Hz;
        const __half* wol  = wo  + (size_t)l * Hz * Hz;
        const __half* wil  = wi  + (size_t)l * Hz * Iz;
        const __half* wo2l = wo2 + (size_t)l * Iz * Hz;

        // Q, K, V projections
        {
            GP p{};
            p.A = xb; p.M = M; p.N = Hz; p.K = Hz;
            p.lda = Hz; p.ldb = Hz; p.ldo = Hz; p.zdiv = 1;
            p.Bm = wql; p.bias = bq + l * Hz; p.outB = q_;
            gemm_k<0, false><<<dim3(Hz/64, M/128, 1), 256>>>(p);
            p.Bm = wkl; p.bias = bk + l * Hz; p.outB = k_;
            gemm_k<0, false><<<dim3(Hz/64, M/128, 1), 256>>>(p);
            p.Bm = wvl; p.bias = bv + l * Hz; p.outB = v_;
            gemm_k<0, false><<<dim3(Hz/64, M/128, 1), 256>>>(p);
        }
        // scores = scale * Q @ K^T  (batched over B*NH)
        {
            GP p{};
            p.A = q_; p.Bm = k_; p.outF = scores;
            p.M = Sz; p.N = Sz; p.K = DHz;
            p.lda = Hz; p.ldb = Hz; p.ldo = Sz; p.zdiv = NHz;
            p.sAo = (long long)Sz * Hz; p.sAi = DHz;
            p.sBo = (long long)Sz * Hz; p.sBi = DHz;
            p.sOo = (long long)NHz * Sz * Sz; p.sOi = (long long)Sz * Sz;
            p.alpha = 0.125f;
            gemm_k<3, true><<<dim3(Sz/64, Sz/128, Bz * NHz), 256>>>(p);
        }
        softmax_k<<<Bz * NHz * Sz, 128>>>(scores, probs);
        // ctx = P @ V (batched)
        {
            GP p{};
            p.A = probs; p.Bm = v_; p.outB = ctx;
            p.M = Sz; p.N = DHz; p.K = Sz;
            p.lda = Sz; p.ldb = Hz; p.ldo = Hz; p.zdiv = NHz;
            p.sAo = (long long)NHz * Sz * Sz; p.sAi = (long long)Sz * Sz;
            p.sBo = (long long)Sz * Hz; p.sBi = DHz;
            p.sOo = (long long)Sz * Hz; p.sOi = DHz;
            gemm_k<0, false><<<dim3(1, Sz/128, Bz * NHz), 256>>>(p);
        }
        // O projection + bias + residual -> tmp (fp32)
        {
            GP p{};
            p.A = ctx; p.Bm = wol; p.bias = bo + l * Hz; p.res = x; p.outF = tmp;
            p.M = M; p.N = Hz; p.K = Hz;
            p.lda = Hz; p.ldb = Hz; p.ldr = Hz; p.ldo = Hz; p.zdiv = 1;
            gemm_k<1, false><<<dim3(Hz/64, M/128, 1), 256>>>(p);
        }
        ln_k<<<Bz * Sz, 256>>>(tmp, ln1g + l * Hz, ln1b + l * Hz, attn, attnb);
        // FFN1 + GELU -> h (fp16)
        {
            GP p{};
            p.A = attnb; p.Bm = wil; p.bias = bi + l * Iz; p.outB = hh;
            p.M = M; p.N = Iz; p.K = Hz;
            p.lda = Hz; p.ldb = Iz; p.ldo = Iz; p.zdiv = 1;
            gemm_k<2, false><<<dim3(Iz/64, M/128, 1), 256>>>(p);
        }
        // FFN2 + bias + residual -> tmp (fp32)
        {
            GP p{};
            p.A = hh; p.Bm = wo2l; p.bias = bo2 + l * Hz; p.res = attn; p.outF = tmp;
            p.M = M; p.N = Hz; p.K = Iz;
            p.lda = Iz; p.ldb = Hz; p.ldr = Hz; p.ldo = Hz; p.zdiv = 1;
            gemm_k<1, false><<<dim3(Hz/64, M/128, 1), 256>>>(p);
        }
        float* outp = (l == Lz - 1) ? (float*)d_out : x;
        ln_k<<<Bz * Sz, 256>>>(tmp, ln2g + l * Hz, ln2b + l * Hz, outp, xb);
    }
}

// round 3
// speedup vs baseline: 1.4184x; 1.4184x over previous
#include <cuda_runtime.h>
#include <cuda_fp16.h>
#include <mma.h>
#include <cstdint>
#include <cstddef>

using namespace nvcuda;

#define Bz 16
#define Sz 512
#define Hz 768
#define Lz 12
#define NHz 12
#define Iz 3072
#define DHz 64
#define BSHz (Bz*Sz*Hz)

// ---------------- scratch (device globals; no allocations allowed) ----------
__device__ __align__(16) float  g_x[BSHz];        // fp32 master activation
__device__ __align__(16) float  g_tmp[BSHz];      // pre-LN buffer
__device__ __align__(16) float  g_attn[BSHz];     // attn_out fp32 (FFN residual)
__device__ __align__(16) __half g_xb[BSHz];
__device__ __align__(16) __half g_attnb[BSHz];
__device__ __align__(16) __half g_qkv[3*BSHz];    // Q,K,V contiguous
__device__ __align__(16) __half g_ctx[BSHz];
__device__ __align__(16) __half g_h[(size_t)Bz*Sz*Iz];
__device__ __align__(16) __half g_wqkv[(size_t)Lz*3*Hz*Hz];  // [L][3][H][H]
__device__ __align__(16) float  g_bqkv[Lz*3*Hz];
__device__ __align__(16) __half g_wo[(size_t)Lz*Hz*Hz];
__device__ __align__(16) __half g_wi[(size_t)Lz*Hz*Iz];
__device__ __align__(16) __half g_wo2[(size_t)Lz*Hz*Iz];

// ---------------- fp32 -> fp16 conversion ----------------------------------
__global__ void f2h_k(const float* __restrict__ s, __half* __restrict__ d, int n4) {
    int i = blockIdx.x * 256 + threadIdx.x;
    if (i < n4) {
        float4 f = ((const float4*)s)[i];
        __half2* dp = (__half2*)d;
        dp[2*i]   = __floats2half2_rn(f.x, f.y);
        dp[2*i+1] = __floats2half2_rn(f.z, f.w);
    }
}

// interleave [L][H][H] fp32 -> [L][3][H][H] fp16 at slot
__global__ void f2h_slot_k(const float* __restrict__ s, __half* __restrict__ d, int slot) {
    int i4 = blockIdx.x * 256 + threadIdx.x;
    const int n4 = Hz * Hz / 4;
    if (i4 < n4) {
        int l = blockIdx.y;
        float4 f = ((const float4*)(s + (size_t)l * Hz * Hz))[i4];
        __half2* dp = (__half2*)(d + ((size_t)l * 3 + slot) * Hz * Hz);
        dp[2*i4]   = __floats2half2_rn(f.x, f.y);
        dp[2*i4+1] = __floats2half2_rn(f.z, f.w);
    }
}

__global__ void bias_slot_k(const float* __restrict__ s, float* __restrict__ d, int slot) {
    int i = blockIdx.x * 256 + threadIdx.x;
    if (i < Lz * Hz) {
        int l = i / Hz, c = i % Hz;
        d[((size_t)l * 3 + slot) * Hz + c] = s[i];
    }
}

// ---------------- block reductions ------------------------------------------
__device__ __forceinline__ float bsum256(float v, float* sm) {
    #pragma unroll
    for (int o = 16; o; o >>= 1) v += __shfl_xor_sync(0xFFFFFFFFu, v, o);
    int t = threadIdx.x;
    if ((t & 31) == 0) sm[t >> 5] = v;
    __syncthreads();
    float r = sm[0];
    #pragma unroll
    for (int i = 1; i < 8; i++) r += sm[i];
    __syncthreads();
    return r;
}

// ---------------- embedding + LN (row per block, 256 thr) ------------------
__global__ void embed_ln_k(const int* __restrict__ ids,
                           const float* __restrict__ we,
                           const float* __restrict__ pe,
                           const float* __restrict__ te,
                           const float* __restrict__ g,
                           const float* __restrict__ b,
                           float* __restrict__ dF,
                           __half* __restrict__ dB) {
    __shared__ float sm[8];
    int row = blockIdx.x;
    int s_ = row & (Sz - 1);
    int id = ids[row];
    int t = threadIdx.x;
    float v[3];
    #pragma unroll
    for (int i = 0; i < 3; i++) {
        int col = t + i * 256;
        v[i] = we[(size_t)id * Hz + col] + pe[(size_t)(s_ + 2) * Hz + col] + te[col];
    }
    float mean = bsum256(v[0] + v[1] + v[2], sm) * (1.0f / Hz);
    float d0 = v[0] - mean, d1 = v[1] - mean, d2 = v[2] - mean;
    float var = bsum256(d0*d0 + d1*d1 + d2*d2, sm) * (1.0f / Hz);
    float rs = rsqrtf(var + 1e-5f);
    size_t base = (size_t)row * Hz;
    #pragma unroll
    for (int i = 0; i < 3; i++) {
        int col = t + i * 256;
        float y = (v[i] - mean) * rs * g[col] + b[col];
        dF[base + col] = y;
        dB[base + col] = __float2half_rn(y);
    }
}

// ---------------- LayerNorm (row per block) ---------------------------------
__global__ void ln_k(const float* __restrict__ src,
                     const float* __restrict__ g,
                     const float* __restrict__ b,
                     float* __restrict__ dF,
                     __half* __restrict__ dB) {
    __shared__ float sm[8];
    size_t base = (size_t)blockIdx.x * Hz;
    int t = threadIdx.x;
    float v[3];
    #pragma unroll
    for (int i = 0; i < 3; i++) v[i] = src[base + t + i * 256];
    float mean = bsum256(v[0] + v[1] + v[2], sm) * (1.0f / Hz);
    float d0 = v[0] - mean, d1 = v[1] - mean, d2 = v[2] - mean;
    float var = bsum256(d0*d0 + d1*d1 + d2*d2, sm) * (1.0f / Hz);
    float rs = rsqrtf(var + 1e-5f);
    #pragma unroll
    for (int i = 0; i < 3; i++) {
        int col = t + i * 256;
        float y = (v[i] - mean) * rs * g[col] + b[col];
        if (dF) dF[base + col] = y;
        dB[base + col] = __float2half_rn(y);
    }
}

// ---------------- cp.async helpers ------------------------------------------
__device__ __forceinline__ void cpa16(uint32_t d, const void* s) {
    asm volatile("cp.async.cg.shared.global [%0], [%1], 16;" :: "r"(d), "l"(s));
}
__device__ __forceinline__ void cpa_commit() {
    asm volatile("cp.async.commit_group;");
}
template<int N>
__device__ __forceinline__ void cpa_wait() {
    asm volatile("cp.async.wait_group %0;" :: "n"(N));
}

// ---------------- batched fp16 GEMM, 128x128x32, 3-stage cp.async ------------
// 256 threads = 8 warps (2x4), warp tile 64x32.
// EPI: 0 outB = half(acc + bias)
//      1 outF = acc + bias + res
//      2 outB = half(gelu(acc + bias))
struct GP {
    const __half* A;
    const __half* Bm;
    const float* bias;
    const float* res;
    float* outF;
    __half* outB;
    int K, lda, ldb, ldr, ldo;
    long long sBi, sBiasI, sOi;   // z strides (QKV fusion)
};

// smem layout: stage s: A at s*10240 (128x40 half), B at 30720 + s*8704 (32x136 half)
// epilogue reuses bytes [0, 67584) as float 128x132
#define GSMEM 67584

template<int EPI>
__global__ void __launch_bounds__(256, 2) gemm_k(GP p) {
    extern __shared__ __align__(16) char smraw[];
    const int tid = threadIdx.x;
    const int wid = tid >> 5;
    const int wm = wid >> 2, wn = wid & 3;

    const int m0 = blockIdx.y * 128, n0 = blockIdx.x * 128;
    const int zi = blockIdx.z;

    const __half* A  = p.A;
    const __half* Bm = p.Bm + (size_t)zi * p.sBi;
    const float* bias = p.bias + (size_t)zi * p.sBiasI;
    __half* outB = p.outB ? p.outB + (size_t)zi * p.sOi : nullptr;
    float*  outF = p.outF;

    // per-thread copy coordinates
    const int ra = tid >> 2, ca = (tid & 3) << 3;       // A: 2 chunks (ra, ra+64)
    const int rb = tid >> 4, cb = (tid & 15) << 3;      // B: 2 chunks (rb, rb+16)
    const __half* Arow = A + (size_t)(m0 + ra) * p.lda + ca;
    const __half* Brow = Bm + (size_t)rb * p.ldb + n0 + cb;
    const size_t Astep2 = (size_t)64 * p.lda;
    const size_t Bstep2 = (size_t)16 * p.ldb;

    uint32_t sbase = (uint32_t)__cvta_generic_to_shared(smraw);
    const uint32_t aA = sbase + ra * 80 + ca * 2;
    const uint32_t aB = sbase + 30720 + rb * 272 + cb * 2;

    const int KT = p.K >> 5;

    auto issue = [&](int kt) {
        int slot = kt % 3;
        const __half* as = Arow + kt * 32;
        cpa16(aA + slot * 10240, as);
        cpa16(aA + slot * 10240 + 5120, as + Astep2);
        const __half* bs = Brow + (size_t)(kt * 32) * p.ldb;
        cpa16(aB + slot * 8704, bs);
        cpa16(aB + slot * 8704 + 4352, bs + Bstep2);
    };

    issue(0); cpa_commit();
    issue(1); cpa_commit();

    wmma::fragment<wmma::accumulator, 16, 16, 16, float> acc[4][2];
    #pragma unroll
    for (int i = 0; i < 4; i++)
        #pragma unroll
        for (int j = 0; j < 2; j++) wmma::fill_fragment(acc[i][j], 0.0f);

    for (int kt = 0; kt < KT; kt++) {
        cpa_wait<1>();
        __syncthreads();
        if (kt + 2 < KT) issue(kt + 2);
        cpa_commit();

        const int slot = kt % 3;
        const __half* sAh = (const __half*)(smraw + slot * 10240);
        const __half* sBh = (const __half*)(smraw + 30720 + slot * 8704);
        #pragma unroll
        for (int kk = 0; kk < 2; kk++) {
            wmma::fragment<wmma::matrix_a, 16, 16, 16, __half, wmma::row_major> af[4];
            #pragma unroll
            for (int i = 0; i < 4; i++)
                wmma::load_matrix_sync(af[i], sAh + (wm * 64 + i * 16) * 40 + kk * 16, 40);
            wmma::fragment<wmma::matrix_b, 16, 16, 16, __half, wmma::row_major> bf[2];
            #pragma unroll
            for (int j = 0; j < 2; j++)
                wmma::load_matrix_sync(bf[j], sBh + (kk * 16) * 136 + wn * 32 + j * 16, 136);
            #pragma unroll
            for (int i = 0; i < 4; i++)
                #pragma unroll
                for (int j = 0; j < 2; j++)
                    wmma::mma_sync(acc[i][j], af[i], bf[j], acc[i][j]);
        }
    }

    __syncthreads();
    float* epi = (float*)smraw;
    #pragma unroll
    for (int i = 0; i < 4; i++)
        #pragma unroll
        for (int j = 0; j < 2; j++)
            wmma::store_matrix_sync(epi + (wm * 64 + i * 16) * 132 + wn * 32 + j * 16,
                                    acc[i][j], 132, wmma::mem_row_major);
    __syncthreads();

    #pragma unroll 4
    for (int e = tid; e < 128 * 128; e += 256) {
        int r = e >> 7, c = e & 127;
        float v = epi[r * 132 + c];
        int gm = m0 + r, gn = n0 + c;
        if (EPI == 0) {
            v += bias[gn];
            outB[(size_t)gm * p.ldo + gn] = __float2half_rn(v);
        } else if (EPI == 1) {
            v += bias[gn] + p.res[(size_t)gm * p.ldr + gn];
            outF[(size_t)gm * p.ldo + gn] = v;
        } else {
            v += bias[gn];
            v = 0.5f * v * (1.0f + erff(v * 0.70710678118654752f));
            outB[(size_t)gm * p.ldo + gn] = __float2half_rn(v);
        }
    }
}

// ---------------- fused flash attention -------------------------------------
// grid (4 q-tiles, B*NH). 256 threads = 8 warps. Q tile 128x64, K/V tiles 64x64.
// smem: sQ 128x72 h | sK 64x72 h | sV 64x72 h | sS 128x68 f (=sP 128x136 h) |
//       sO 128x68 f | m/f/l vectors
#define FSMEM 108032

__global__ void __launch_bounds__(256, 2) flash_k(const __half* __restrict__ qkv,
                                                  __half* __restrict__ ctx) {
    extern __shared__ __align__(16) char sm[];
    __half* sQ = (__half*)sm;
    __half* sK = (__half*)(sm + 18432);
    __half* sV = (__half*)(sm + 27648);
    float*  sS = (float*)(sm + 36864);
    __half* sP = (__half*)(sm + 36864);
    float*  sO = (float*)(sm + 71680);
    float*  sMm = (float*)(sm + 106496);
    float*  sF = sMm + 128;
    float*  sL = sF + 128;

    const int tid = threadIdx.x;
    const int wid = tid >> 5;
    const int wm = wid >> 1, wn = wid & 1;
    const int qt = blockIdx.x;
    const int z = blockIdx.y;
    const int b = z / NHz, h = z % NHz;

    const size_t qoff = ((size_t)b * Sz) * Hz + h * DHz;
    const __half* Qp = qkv + qoff;
    const __half* Kp = qkv + (size_t)BSHz + qoff;
    const __half* Vp = qkv + 2 * (size_t)BSHz + qoff;

    // load Q tile 128x64
    #pragma unroll
    for (int s = 0; s < 4; s++) {
        int ch = tid + s * 256;
        int r = ch >> 3, c = (ch & 7) << 3;
        *(uint4*)(sQ + r * 72 + c) = *(const uint4*)(Qp + (size_t)(qt * 128 + r) * Hz + c);
    }
    // init O, m, l
    #pragma unroll
    for (int s = 0; s < 32; s++) {
        int e = tid + s * 256;
        sO[(e >> 6) * 68 + (e & 63)] = 0.0f;
    }
    if (tid < 128) { sMm[tid] = -1e30f; sL[tid] = 0.0f; }

    const int r = tid >> 1, hf = tid & 1;

    for (int kt = 0; kt < 8; kt++) {
        // load K,V tiles 64x64
        #pragma unroll
        for (int s = 0; s < 2; s++) {
            int ch = tid + s * 256;
            int rr = ch >> 3, c = (ch & 7) << 3;
            size_t go = (size_t)(kt * 64 + rr) * Hz + c;
            *(uint4*)(sK + rr * 72 + c) = *(const uint4*)(Kp + go);
            *(uint4*)(sV + rr * 72 + c) = *(const uint4*)(Vp + go);
        }
        __syncthreads();

        // S = Q @ K^T : warp (wm 0..3, wn 0..1) -> rows wm*32, cols wn*32
        {
            wmma::fragment<wmma::accumulator, 16, 16, 16, float> sacc[2][2];
            #pragma unroll
            for (int i = 0; i < 2; i++)
                #pragma unroll
                for (int j = 0; j < 2; j++) wmma::fill_fragment(sacc[i][j], 0.0f);
            #pragma unroll
            for (int k = 0; k < 4; k++) {
                wmma::fragment<wmma::matrix_a, 16, 16, 16, __half, wmma::row_major> a[2];
                wmma::fragment<wmma::matrix_b, 16, 16, 16, __half, wmma::col_major> bb[2];
                #pragma unroll
                for (int i = 0; i < 2; i++)
                    wmma::load_matrix_sync(a[i], sQ + (wm * 32 + i * 16) * 72 + k * 16, 72);
                #pragma unroll
                for (int j = 0; j < 2; j++)
                    wmma::load_matrix_sync(bb[j], sK + (wn * 32 + j * 16) * 72 + k * 16, 72);
                #pragma unroll
                for (int i = 0; i < 2; i++)
                    #pragma unroll
                    for (int j = 0; j < 2; j++)
                        wmma::mma_sync(sacc[i][j], a[i], bb[j], sacc[i][j]);
            }
            #pragma unroll
            for (int i = 0; i < 2; i++)
                #pragma unroll
                for (int j = 0; j < 2; j++)
                    wmma::store_matrix_sync(sS + (wm * 32 + i * 16) * 68 + wn * 32 + j * 16,
                                            sacc[i][j], 68, wmma::mem_row_major);
        }
        __syncthreads();

        // online softmax on 64-wide tile: 2 threads per row
        {
            float pv[32];
            float mold = sMm[r];
            float tmax = -1e30f;
            #pragma unroll
            for (int c = 0; c < 32; c++) {
                float s = sS[r * 68 + hf * 32 + c] * 0.125f;
                pv[c] = s;
                tmax = fmaxf(tmax, s);
            }
            tmax = fmaxf(tmax, __shfl_xor_sync(0xFFFFFFFFu, tmax, 1));
            float mnew = fmaxf(mold, tmax);
            float lsum = 0.0f;
            #pragma unroll
            for (int c = 0; c < 32; c++) {
                pv[c] = __expf(pv[c] - mnew);
                lsum += pv[c];
            }
            lsum += __shfl_xor_sync(0xFFFFFFFFu, lsum, 1);
            __syncwarp();
            #pragma unroll
            for (int c = 0; c < 32; c++)
                sP[r * 136 + hf * 32 + c] = __float2half_rn(pv[c]);
            if (!hf) {
                float f = __expf(mold - mnew);
                sF[r] = f;
                sMm[r] = mnew;
                sL[r] = sL[r] * f + lsum;
            }
        }
        __syncthreads();

        // PV = P @ V
        {
            wmma::fragment<wmma::accumulator, 16, 16, 16, float> oacc[2][2];
            #pragma unroll
            for (int i = 0; i < 2; i++)
                #pragma unroll
                for (int j = 0; j < 2; j++) wmma::fill_fragment(oacc[i][j], 0.0f);
            #pragma unroll
            for (int k = 0; k < 4; k++) {
                wmma::fragment<wmma::matrix_a, 16, 16, 16, __half, wmma::row_major> a[2];
                wmma::fragment<wmma::matrix_b, 16, 16, 16, __half, wmma::row_major> bb[2];
                #pragma unroll
                for (int i = 0; i < 2; i++)
                    wmma::load_matrix_sync(a[i], sP + (wm * 32 + i * 16) * 136 + k * 16, 136);
                #pragma unroll
                for (int j = 0; j < 2; j++)
                    wmma::load_matrix_sync(bb[j], sV + (k * 16) * 72 + wn * 32 + j * 16, 72);
                #pragma unroll
                for (int i = 0; i < 2; i++)
                    #pragma unroll
                    for (int j = 0; j < 2; j++)
                        wmma::mma_sync(oacc[i][j], a[i], bb[j], oacc[i][j]);
            }
            __syncthreads();   // all P reads done before overwriting sS region
            #pragma unroll
            for (int i = 0; i < 2; i++)
                #pragma unroll
                for (int j = 0; j < 2; j++)
                    wmma::store_matrix_sync(sS + (wm * 32 + i * 16) * 68 + wn * 32 + j * 16,
                                            oacc[i][j], 68, wmma::mem_row_major);
        }
        __syncthreads();

        // O = O * f + PV
        {
            float f = sF[r];
            #pragma unroll
            for (int c = 0; c < 32; c++) {
                int idx = r * 68 + hf * 32 + c;
                sO[idx] = sO[idx] * f + sS[idx];
            }
        }
        __syncthreads();
    }

    // write ctx = O / l
    {
        float inv = 1.0f / sL[r];
        __half* dst = ctx + ((size_t)(b * Sz) + qt * 128 + r) * Hz + h * DHz + hf * 32;
        #pragma unroll
        for (int c = 0; c < 32; c++)
            dst[c] = __float2half_rn(sO[r * 68 + hf * 32 + c] * inv);
    }
}

// ---------------- host orchestration ----------------------------------------
extern "C" void kernel_launch(void* const* d_in, const int* in_sizes, int n_in,
                              void* d_out, int out_size) {
    const int*   ids   = (const int*)d_in[0];
    const float* word  = (const float*)d_in[1];
    const float* pos   = (const float*)d_in[2];
    const float* type0 = (const float*)d_in[3];
    const float* lneg  = (const float*)d_in[4];
    const float* lneb  = (const float*)d_in[5];
    const float* Wq    = (const float*)d_in[6];
    const float* bq    = (const float*)d_in[7];
    const float* Wk    = (const float*)d_in[8];
    const float* bk    = (const float*)d_in[9];
    const float* Wv    = (const float*)d_in[10];
    const float* bv    = (const float*)d_in[11];
    const float* Wo    = (const float*)d_in[12];
    const float* bo    = (const float*)d_in[13];
    const float* ln1g  = (const float*)d_in[14];
    const float* ln1b  = (const float*)d_in[15];
    const float* Wi    = (const float*)d_in[16];
    const float* bi    = (const float*)d_in[17];
    const float* Wo2   = (const float*)d_in[18];
    const float* bo2   = (const float*)d_in[19];
    const float* ln2g  = (const float*)d_in[20];
    const float* ln2b  = (const float*)d_in[21];

    float *x, *tmp, *attn, *bqkv;
    __half *xb, *attnb, *qkv, *ctx, *hh, *wqkv, *wo, *wi, *wo2;
    cudaGetSymbolAddress((void**)&x,     g_x);
    cudaGetSymbolAddress((void**)&tmp,   g_tmp);
    cudaGetSymbolAddress((void**)&attn,  g_attn);
    cudaGetSymbolAddress((void**)&bqkv,  g_bqkv);
    cudaGetSymbolAddress((void**)&xb,    g_xb);
    cudaGetSymbolAddress((void**)&attnb, g_attnb);
    cudaGetSymbolAddress((void**)&qkv,   g_qkv);
    cudaGetSymbolAddress((void**)&ctx,   g_ctx);
    cudaGetSymbolAddress((void**)&hh,    g_h);
    cudaGetSymbolAddress((void**)&wqkv,  g_wqkv);
    cudaGetSymbolAddress((void**)&wo,    g_wo);
    cudaGetSymbolAddress((void**)&wi,    g_wi);
    cudaGetSymbolAddress((void**)&wo2,   g_wo2);

    cudaFuncSetAttribute(gemm_k<0>, cudaFuncAttributeMaxDynamicSharedMemorySize, GSMEM);
    cudaFuncSetAttribute(gemm_k<1>, cudaFuncAttributeMaxDynamicSharedMemorySize, GSMEM);
    cudaFuncSetAttribute(gemm_k<2>, cudaFuncAttributeMaxDynamicSharedMemorySize, GSMEM);
    cudaFuncSetAttribute(flash_k,   cudaFuncAttributeMaxDynamicSharedMemorySize, FSMEM);

    // weight conversions: QKV interleaved [L][3][H][H]
    {
        dim3 gs((Hz * Hz / 4 + 255) / 256, Lz);
        f2h_slot_k<<<gs, 256>>>(Wq, wqkv, 0);
        f2h_slot_k<<<gs, 256>>>(Wk, wqkv, 1);
        f2h_slot_k<<<gs, 256>>>(Wv, wqkv, 2);
        int nb = (Lz * Hz + 255) / 256;
        bias_slot_k<<<nb, 256>>>(bq, bqkv, 0);
        bias_slot_k<<<nb, 256>>>(bk, bqkv, 1);
        bias_slot_k<<<nb, 256>>>(bv, bqkv, 2);
    }
    auto conv = [&](const float* src, __half* dst, size_t n) {
        int n4 = (int)(n / 4);
        f2h_k<<<(n4 + 255) / 256, 256>>>(src, dst, n4);
    };
    conv(Wo,  wo,  (size_t)Lz * Hz * Hz);
    conv(Wi,  wi,  (size_t)Lz * Hz * Iz);
    conv(Wo2, wo2, (size_t)Lz * Hz * Iz);

    embed_ln_k<<<Bz * Sz, 256>>>(ids, word, pos, type0, lneg, lneb, x, xb);

    const int M = Bz * Sz; // 8192
    for (int l = 0; l < Lz; l++) {
        // fused QKV projection (z = 0,1,2)
        {
            GP p{};
            p.A = xb;
            p.Bm = wqkv + (size_t)l * 3 * Hz * Hz;
            p.bias = bqkv + (size_t)l * 3 * Hz;
            p.outB = qkv;
            p.K = Hz; p.lda = Hz; p.ldb = Hz; p.ldo = Hz;
            p.sBi = (long long)Hz * Hz;
            p.sBiasI = Hz;
            p.sOi = (long long)BSHz;
            gemm_k<0><<<dim3(Hz/128, M/128, 3), 256, GSMEM>>>(p);
        }
        // fused flash attention -> ctx
        flash_k<<<dim3(Sz/128, Bz*NHz), 256, FSMEM>>>(qkv, ctx);
        // O projection + bias + residual -> tmp (fp32)
        {
            GP p{};
            p.A = ctx;
            p.Bm = wo + (size_t)l * Hz * Hz;
            p.bias = bo + l * Hz;
            p.res = x; p.outF = tmp;
            p.K = Hz; p.lda = Hz; p.ldb = Hz; p.ldr = Hz; p.ldo = Hz;
            gemm_k<1><<<dim3(Hz/128, M/128, 1), 256, GSMEM>>>(p);
        }
        ln_k<<<Bz * Sz, 256>>>(tmp, ln1g + l * Hz, ln1b + l * Hz, attn, attnb);
        // FFN1 + GELU -> h (fp16)
        {
            GP p{};
            p.A = attnb;
            p.Bm = wi + (size_t)l * Hz * Iz;
            p.bias = bi + l * Iz;
            p.outB = hh;
            p.K = Hz; p.lda = Hz; p.ldb = Iz; p.ldo = Iz;
            gemm_k<2><<<dim3(Iz/128, M/128, 1), 256, GSMEM>>>(p);
        }
        // FFN2 + bias + residual -> tmp (fp32)
        {
            GP p{};
            p.A = hh;
            p.Bm = wo2 + (size_t)l * Iz * Hz;
            p.bias = bo2 + l * Hz;
            p.res = attn; p.outF = tmp;
            p.K = Iz; p.lda = Iz; p.ldb = Hz; p.ldr = Hz; p.ldo = Hz;
            gemm_k<1><<<dim3(Hz/128, M/128, 1), 256, GSMEM>>>(p);
        }
        float* outp = (l == Lz - 1) ? (float*)d_out : x;
        ln_k<<<Bz * Sz, 256>>>(tmp, ln2g + l * Hz, ln2b + l * Hz, outp, xb);
    }
}

// round 5
// speedup vs baseline: 1.5060x; 1.0618x over previous
#include <cuda_runtime.h>
#include <cuda_fp16.h>
#include <mma.h>
#include <cstdint>
#include <cstddef>

using namespace nvcuda;

#define Bz 16
#define Sz 512
#define Hz 768
#define Lz 12
#define NHz 12
#define Iz 3072
#define DHz 64
#define BSHz (Bz*Sz*Hz)
#define QLD 2304

// ---------------- scratch (device globals; no allocations allowed) ----------
__device__ __align__(16) float  g_x[BSHz];
__device__ __align__(16) float  g_tmp[BSHz];
__device__ __align__(16) float  g_attn[BSHz];
__device__ __align__(16) __half g_xb[BSHz];
__device__ __align__(16) __half g_attnb[BSHz];
__device__ __align__(16) __half g_qkv[3*BSHz];            // [8192][2304]
__device__ __align__(16) __half g_ctx[BSHz];
__device__ __align__(16) __half g_h[(size_t)Bz*Sz*Iz];
__device__ __align__(16) __half g_wqkvT[(size_t)Lz*3*Hz*Hz];   // [L][2304][768]
__device__ __align__(16) __half g_woT[(size_t)Lz*Hz*Hz];       // [L][768][768]
__device__ __align__(16) __half g_wiT[(size_t)Lz*Hz*Iz];       // [L][3072][768]
__device__ __align__(16) __half g_wo2T[(size_t)Lz*Hz*Iz];      // [L][768][3072]

// ---------------- cp.async helpers ------------------------------------------
__device__ __forceinline__ void cpa16(uint32_t d, const void* s) {
    asm volatile("cp.async.cg.shared.global [%0], [%1], 16;" :: "r"(d), "l"(s));
}
__device__ __forceinline__ void cpa_commit() { asm volatile("cp.async.commit_group;"); }
template<int N> __device__ __forceinline__ void cpa_wait() {
    asm volatile("cp.async.wait_group %0;" :: "n"(N));
}

// ---------------- weight transpose + fp32->fp16 ------------------------------
// src [R,C] fp32 (slice z) -> dst [C,R] fp16 (slice z)
__global__ void transpose_f2h_k(const float* __restrict__ src, __half* __restrict__ dst,
                                int R, int C) {
    __shared__ float t[32][33];
    int bx = blockIdx.x * 32, by = blockIdx.y * 32;
    const float* s = src + (size_t)blockIdx.z * R * C;
    __half* d = dst + (size_t)blockIdx.z * R * C;
    int tx = threadIdx.x, ty = threadIdx.y;
    #pragma unroll
    for (int i = 0; i < 32; i += 8)
        t[ty + i][tx] = s[(size_t)(by + ty + i) * C + bx + tx];
    __syncthreads();
    #pragma unroll
    for (int i = 0; i < 32; i += 8)
        d[(size_t)(bx + ty + i) * R + by + tx] = __float2half_rn(t[tx][ty + i]);
}

// QKV: 3 sources -> [L][2304][768] fp16 (each slot transposed)
__global__ void transpose_qkv_k(const float* __restrict__ q, const float* __restrict__ k,
                                const float* __restrict__ v, __half* __restrict__ dst) {
    __shared__ float t[32][33];
    int z = blockIdx.z;
    int slot = z / Lz, l = z % Lz;
    const float* srcs = (slot == 0 ? q : (slot == 1 ? k : v)) + (size_t)l * Hz * Hz;
    __half* d = dst + ((size_t)l * 3 + slot) * Hz * Hz;
    int bx = blockIdx.x * 32, by = blockIdx.y * 32;
    int tx = threadIdx.x, ty = threadIdx.y;
    #pragma unroll
    for (int i = 0; i < 32; i += 8)
        t[ty + i][tx] = srcs[(size_t)(by + ty + i) * Hz + bx + tx];
    __syncthreads();
    #pragma unroll
    for (int i = 0; i < 32; i += 8)
        d[(size_t)(bx + ty + i) * Hz + by + tx] = __float2half_rn(t[tx][ty + i]);
}

// ---------------- block reductions ------------------------------------------
__device__ __forceinline__ float bsum256(float v, float* sm) {
    #pragma unroll
    for (int o = 16; o; o >>= 1) v += __shfl_xor_sync(0xFFFFFFFFu, v, o);
    int t = threadIdx.x;
    if ((t & 31) == 0) sm[t >> 5] = v;
    __syncthreads();
    float r = sm[0];
    #pragma unroll
    for (int i = 1; i < 8; i++) r += sm[i];
    __syncthreads();
    return r;
}

// ---------------- embedding + LN ---------------------------------------------
__global__ void embed_ln_k(const int* __restrict__ ids,
                           const float* __restrict__ we,
                           const float* __restrict__ pe,
                           const float* __restrict__ te,
                           const float* __restrict__ g,
                           const float* __restrict__ b,
                           float* __restrict__ dF,
                           __half* __restrict__ dB) {
    __shared__ float sm[8];
    int row = blockIdx.x;
    int s_ = row & (Sz - 1);
    int id = ids[row];
    int t = threadIdx.x;
    float v[3];
    #pragma unroll
    for (int i = 0; i < 3; i++) {
        int col = t + i * 256;
        v[i] = we[(size_t)id * Hz + col] + pe[(size_t)(s_ + 2) * Hz + col] + te[col];
    }
    float mean = bsum256(v[0] + v[1] + v[2], sm) * (1.0f / Hz);
    float d0 = v[0] - mean, d1 = v[1] - mean, d2 = v[2] - mean;
    float var = bsum256(d0*d0 + d1*d1 + d2*d2, sm) * (1.0f / Hz);
    float rs = rsqrtf(var + 1e-5f);
    size_t base = (size_t)row * Hz;
    #pragma unroll
    for (int i = 0; i < 3; i++) {
        int col = t + i * 256;
        float y = (v[i] - mean) * rs * g[col] + b[col];
        dF[base + col] = y;
        dB[base + col] = __float2half_rn(y);
    }
}

// ---------------- LayerNorm ---------------------------------------------------
__global__ void ln_k(const float* __restrict__ src,
                     const float* __restrict__ g,
                     const float* __restrict__ b,
                     float* __restrict__ dF,
                     __half* __restrict__ dB) {
    __shared__ float sm[8];
    size_t base = (size_t)blockIdx.x * Hz;
    int t = threadIdx.x;
    float v[3];
    #pragma unroll
    for (int i = 0; i < 3; i++) v[i] = src[base + t + i * 256];
    float mean = bsum256(v[0] + v[1] + v[2], sm) * (1.0f / Hz);
    float d0 = v[0] - mean, d1 = v[1] - mean, d2 = v[2] - mean;
    float var = bsum256(d0*d0 + d1*d1 + d2*d2, sm) * (1.0f / Hz);
    float rs = rsqrtf(var + 1e-5f);
    #pragma unroll
    for (int i = 0; i < 3; i++) {
        int col = t + i * 256;
        float y = (v[i] - mean) * rs * g[col] + b[col];
        if (dF) dF[base + col] = y;
        dB[base + col] = __float2half_rn(y);
    }
}

// ---------------- HMMA GEMM: 128x128 tile, 4 warps of 64x64, 3-stage ---------
// A [M, K] fp16 K-major (lda=K). Bt [N, K] fp16 K-major (ldb=K).
// grid (N/128, M/128), 128 threads.
// EPI: 0 outB = half(acc + bias)   (bias1/bias2: QKV slot biases by column)
//      1 outF = acc + bias + res   2 outB = half(gelu(acc + bias))
struct GP {
    const __half* A;
    const __half* Bt;
    const float* bias;
    const float* bias1;
    const float* bias2;
    const float* res;
    float* outF;
    __half* outB;
    int K, ldo;
};

// stage s at s*20480: A tile 128x32 (pad 40) = 10240 B, B tile 128x32 (pad 40) = 10240 B
// epilogue reuses [0, 67584) as float 128x132
#define GSMEM 67584

template<int EPI>
__global__ void __launch_bounds__(128, 2) hgemm_k(GP p) {
    extern __shared__ __align__(16) char smraw[];
    const int tid = threadIdx.x;
    const int wid = tid >> 5;
    const int wm = wid >> 1, wn = wid & 1;     // 2x2 warp grid, 64x64 each
    const int m0 = blockIdx.y * 128, n0 = blockIdx.x * 128;

    const __half* Arow = p.A + (size_t)m0 * p.K;
    const __half* Brow = p.Bt + (size_t)n0 * p.K;
    const int K = p.K, KT = K >> 5;

    uint32_t sbase = (uint32_t)__cvta_generic_to_shared(smraw);

    // 512 16B chunks per matrix per stage; 128 threads -> 4 each.
    // chunk g: row g>>2, 16B-col g&3; smem row pitch 80 B (40 halves)
    auto issue = [&](int kt, int st) {
        const __half* as = Arow + kt * 32;
        const __half* bs = Brow + kt * 32;
        const uint32_t sa = sbase + st * 20480;
        const uint32_t sb = sa + 10240;
        #pragma unroll
        for (int i = 0; i < 4; i++) {
            int g = tid + i * 128;
            int r = g >> 2, c = g & 3;
            cpa16(sa + r * 80 + c * 16, as + (size_t)r * K + c * 8);
            cpa16(sb + r * 80 + c * 16, bs + (size_t)r * K + c * 8);
        }
    };

    issue(0, 0); cpa_commit();
    issue(1, 1); cpa_commit();

    wmma::fragment<wmma::accumulator, 16, 16, 16, float> acc[4][4];
    #pragma unroll
    for (int i = 0; i < 4; i++)
        #pragma unroll
        for (int j = 0; j < 4; j++) wmma::fill_fragment(acc[i][j], 0.0f);

    for (int kt = 0; kt < KT; kt++) {
        cpa_wait<1>();
        __syncthreads();
        if (kt + 2 < KT) issue(kt + 2, (kt + 2) % 3);
        cpa_commit();

        const int st = kt % 3;
        const __half* sA = (const __half*)(smraw + st * 20480);
        const __half* sB = sA + 5120;   // 10240 bytes
        #pragma unroll
        for (int kk = 0; kk < 2; kk++) {
            wmma::fragment<wmma::matrix_a, 16, 16, 16, __half, wmma::row_major> af[4];
            #pragma unroll
            for (int i = 0; i < 4; i++)
                wmma::load_matrix_sync(af[i], sA + (wm * 64 + i * 16) * 40 + kk * 16, 40);
            wmma::fragment<wmma::matrix_b, 16, 16, 16, __half, wmma::col_major> bf[4];
            #pragma unroll
            for (int j = 0; j < 4; j++)
                wmma::load_matrix_sync(bf[j], sB + (wn * 64 + j * 16) * 40 + kk * 16, 40);
            #pragma unroll
            for (int i = 0; i < 4; i++)
                #pragma unroll
                for (int j = 0; j < 4; j++)
                    wmma::mma_sync(acc[i][j], af[i], bf[j], acc[i][j]);
        }
    }

    __syncthreads();
    float* epi = (float*)smraw;
    #pragma unroll
    for (int i = 0; i < 4; i++)
        #pragma unroll
        for (int j = 0; j < 4; j++)
            wmma::store_matrix_sync(epi + (wm * 64 + i * 16) * 132 + wn * 64 + j * 16,
                                    acc[i][j], 132, wmma::mem_row_major);
    __syncthreads();

    // epilogue: thread t handles row t (128 cols)
    {
        const float* ep = epi + tid * 132;
        const int gm = m0 + tid;
        if (EPI == 1) {
            float* orow = p.outF + (size_t)gm * p.ldo + n0;
            const float* rrow = p.res + (size_t)gm * p.ldo + n0;
            #pragma unroll 8
            for (int c = 0; c < 128; c += 4) {
                float4 r4 = *(const float4*)(rrow + c);
                float4 o;
                o.x = ep[c]     + p.bias[n0 + c]     + r4.x;
                o.y = ep[c + 1] + p.bias[n0 + c + 1] + r4.y;
                o.z = ep[c + 2] + p.bias[n0 + c + 2] + r4.z;
                o.w = ep[c + 3] + p.bias[n0 + c + 3] + r4.w;
                *(float4*)(orow + c) = o;
            }
        } else {
            __half* orow = p.outB + (size_t)gm * p.ldo + n0;
            #pragma unroll 4
            for (int c0 = 0; c0 < 128; c0 += 8) {
                float f[8];
                #pragma unroll
                for (int j = 0; j < 8; j++) {
                    int n = n0 + c0 + j;
                    float bv;
                    if (EPI == 0 && p.bias1) {
                        const float* bp = n < 768 ? p.bias : (n < 1536 ? p.bias1 : p.bias2);
                        bv = bp[n & 767];
                    } else {
                        bv = p.bias[n];
                    }
                    f[j] = ep[c0 + j] + bv;
                }
                if (EPI == 2) {
                    #pragma unroll
                    for (int j = 0; j < 8; j++)
                        f[j] = 0.5f * f[j] * (1.0f + erff(f[j] * 0.70710678118654752f));
                }
                __half2 h[4];
                #pragma unroll
                for (int j = 0; j < 4; j++) h[j] = __floats2half2_rn(f[2*j], f[2*j+1]);
                *(uint4*)(orow + c0) = *(uint4*)h;
            }
        }
    }
}

// ---------------- fused flash attention (wmma) -------------------------------
// qkv buffer layout: [8192 rows][2304] halves; Q cols [0,768), K [768,1536), V [1536,2304)
#define FSMEM 108032

__global__ void __launch_bounds__(256, 2) flash_k(const __half* __restrict__ qkv,
                                                  __half* __restrict__ ctx) {
    extern __shared__ __align__(16) char sm[];
    __half* sQ = (__half*)sm;
    __half* sK = (__half*)(sm + 18432);
    __half* sV = (__half*)(sm + 27648);
    float*  sS = (float*)(sm + 36864);
    __half* sP = (__half*)(sm + 36864);
    float*  sO = (float*)(sm + 71680);
    float*  sMm = (float*)(sm + 106496);
    float*  sF = sMm + 128;
    float*  sL = sF + 128;

    const int tid = threadIdx.x;
    const int wid = tid >> 5;
    const int wm = wid >> 1, wn = wid & 1;
    const int qt = blockIdx.x;
    const int z = blockIdx.y;
    const int b = z / NHz, h = z % NHz;

    const __half* Qp = qkv + (size_t)(b * Sz) * QLD + h * DHz;
    const __half* Kp = Qp + 768;
    const __half* Vp = Qp + 1536;

    #pragma unroll
    for (int s = 0; s < 4; s++) {
        int ch = tid + s * 256;
        int r = ch >> 3, c = (ch & 7) << 3;
        *(uint4*)(sQ + r * 72 + c) = *(const uint4*)(Qp + (size_t)(qt * 128 + r) * QLD + c);
    }
    #pragma unroll
    for (int s = 0; s < 32; s++) {
        int e = tid + s * 256;
        sO[(e >> 6) * 68 + (e & 63)] = 0.0f;
    }
    if (tid < 128) { sMm[tid] = -1e30f; sL[tid] = 0.0f; }

    const int r = tid >> 1, hf = tid & 1;

    for (int kt = 0; kt < 8; kt++) {
        #pragma unroll
        for (int s = 0; s < 2; s++) {
            int ch = tid + s * 256;
            int rr = ch >> 3, c = (ch & 7) << 3;
            size_t go = (size_t)(kt * 64 + rr) * QLD + c;
            *(uint4*)(sK + rr * 72 + c) = *(const uint4*)(Kp + go);
            *(uint4*)(sV + rr * 72 + c) = *(const uint4*)(Vp + go);
        }
        __syncthreads();

        {
            wmma::fragment<wmma::accumulator, 16, 16, 16, float> sacc[2][2];
            #pragma unroll
            for (int i = 0; i < 2; i++)
                #pragma unroll
                for (int j = 0; j < 2; j++) wmma::fill_fragment(sacc[i][j], 0.0f);
            #pragma unroll
            for (int k = 0; k < 4; k++) {
                wmma::fragment<wmma::matrix_a, 16, 16, 16, __half, wmma::row_major> a[2];
                wmma::fragment<wmma::matrix_b, 16, 16, 16, __half, wmma::col_major> bb[2];
                #pragma unroll
                for (int i = 0; i < 2; i++)
                    wmma::load_matrix_sync(a[i], sQ + (wm * 32 + i * 16) * 72 + k * 16, 72);
                #pragma unroll
                for (int j = 0; j < 2; j++)
                    wmma::load_matrix_sync(bb[j], sK + (wn * 32 + j * 16) * 72 + k * 16, 72);
                #pragma unroll
                for (int i = 0; i < 2; i++)
                    #pragma unroll
                    for (int j = 0; j < 2; j++)
                        wmma::mma_sync(sacc[i][j], a[i], bb[j], sacc[i][j]);
            }
            #pragma unroll
            for (int i = 0; i < 2; i++)
                #pragma unroll
                for (int j = 0; j < 2; j++)
                    wmma::store_matrix_sync(sS + (wm * 32 + i * 16) * 68 + wn * 32 + j * 16,
                                            sacc[i][j], 68, wmma::mem_row_major);
        }
        __syncthreads();

        {
            float pv[32];
            float mold = sMm[r];
            float tmax = -1e30f;
            #pragma unroll
            for (int c = 0; c < 32; c++) {
                float s = sS[r * 68 + hf * 32 + c] * 0.125f;
                pv[c] = s;
                tmax = fmaxf(tmax, s);
            }
            tmax = fmaxf(tmax, __shfl_xor_sync(0xFFFFFFFFu, tmax, 1));
            float mnew = fmaxf(mold, tmax);
            float lsum = 0.0f;
            #pragma unroll
            for (int c = 0; c < 32; c++) {
                pv[c] = __expf(pv[c] - mnew);
                lsum += pv[c];
            }
            lsum += __shfl_xor_sync(0xFFFFFFFFu, lsum, 1);
            __syncwarp();
            #pragma unroll
            for (int c = 0; c < 32; c++)
                sP[r * 136 + hf * 32 + c] = __float2half_rn(pv[c]);
            if (!hf) {
                float f = __expf(mold - mnew);
                sF[r] = f;
                sMm[r] = mnew;
                sL[r] = sL[r] * f + lsum;
            }
        }
        __syncthreads();

        {
            wmma::fragment<wmma::accumulator, 16, 16, 16, float> oacc[2][2];
            #pragma unroll
            for (int i = 0; i < 2; i++)
                #pragma unroll
                for (int j = 0; j < 2; j++) wmma::fill_fragment(oacc[i][j], 0.0f);
            #pragma unroll
            for (int k = 0; k < 4; k++) {
                wmma::fragment<wmma::matrix_a, 16, 16, 16, __half, wmma::row_major> a[2];
                wmma::fragment<wmma::matrix_b, 16, 16, 16, __half, wmma::row_major> bb[2];
                #pragma unroll
                for (int i = 0; i < 2; i++)
                    wmma::load_matrix_sync(a[i], sP + (wm * 32 + i * 16) * 136 + k * 16, 136);
                #pragma unroll
                for (int j = 0; j < 2; j++)
                    wmma::load_matrix_sync(bb[j], sV + (k * 16) * 72 + wn * 32 + j * 16, 72);
                #pragma unroll
                for (int i = 0; i < 2; i++)
                    #pragma unroll
                    for (int j = 0; j < 2; j++)
                        wmma::mma_sync(oacc[i][j], a[i], bb[j], oacc[i][j]);
            }
            __syncthreads();
            #pragma unroll
            for (int i = 0; i < 2; i++)
                #pragma unroll
                for (int j = 0; j < 2; j++)
                    wmma::store_matrix_sync(sS + (wm * 32 + i * 16) * 68 + wn * 32 + j * 16,
                                            oacc[i][j], 68, wmma::mem_row_major);
        }
        __syncthreads();

        {
            float f = sF[r];
            #pragma unroll
            for (int c = 0; c < 32; c++) {
                int idx = r * 68 + hf * 32 + c;
                sO[idx] = sO[idx] * f + sS[idx];
            }
        }
        __syncthreads();
    }

    {
        float inv = 1.0f / sL[r];
        __half* dst = ctx + ((size_t)(b * Sz) + qt * 128 + r) * Hz + h * DHz + hf * 32;
        #pragma unroll
        for (int c = 0; c < 32; c++)
            dst[c] = __float2half_rn(sO[r * 68 + hf * 32 + c] * inv);
    }
}

// ---------------- host orchestration ----------------------------------------
extern "C" void kernel_launch(void* const* d_in, const int* in_sizes, int n_in,
                              void* d_out, int out_size) {
    const int*   ids   = (const int*)d_in[0];
    const float* word  = (const float*)d_in[1];
    const float* pos   = (const float*)d_in[2];
    const float* type0 = (const float*)d_in[3];
    const float* lneg  = (const float*)d_in[4];
    const float* lneb  = (const float*)d_in[5];
    const float* Wq    = (const float*)d_in[6];
    const float* bq    = (const float*)d_in[7];
    const float* Wk    = (const float*)d_in[8];
    const float* bk    = (const float*)d_in[9];
    const float* Wv    = (const float*)d_in[10];
    const float* bv    = (const float*)d_in[11];
    const float* Wo    = (const float*)d_in[12];
    const float* bo    = (const float*)d_in[13];
    const float* ln1g  = (const float*)d_in[14];
    const float* ln1b  = (const float*)d_in[15];
    const float* Wi    = (const float*)d_in[16];
    const float* bi    = (const float*)d_in[17];
    const float* Wo2   = (const float*)d_in[18];
    const float* bo2   = (const float*)d_in[19];
    const float* ln2g  = (const float*)d_in[20];
    const float* ln2b  = (const float*)d_in[21];

    float *x, *tmp, *attn;
    __half *xb, *attnb, *qkv, *ctx, *hh, *wqkvT, *woT, *wiT, *wo2T;
    cudaGetSymbolAddress((void**)&x,     g_x);
    cudaGetSymbolAddress((void**)&tmp,   g_tmp);
    cudaGetSymbolAddress((void**)&attn,  g_attn);
    cudaGetSymbolAddress((void**)&xb,    g_xb);
    cudaGetSymbolAddress((void**)&attnb, g_attnb);
    cudaGetSymbolAddress((void**)&qkv,   g_qkv);
    cudaGetSymbolAddress((void**)&ctx,   g_ctx);
    cudaGetSymbolAddress((void**)&hh,    g_h);
    cudaGetSymbolAddress((void**)&wqkvT, g_wqkvT);
    cudaGetSymbolAddress((void**)&woT,   g_woT);
    cudaGetSymbolAddress((void**)&wiT,   g_wiT);
    cudaGetSymbolAddress((void**)&wo2T,  g_wo2T);

    cudaFuncSetAttribute(hgemm_k<0>, cudaFuncAttributeMaxDynamicSharedMemorySize, GSMEM);
    cudaFuncSetAttribute(hgemm_k<1>, cudaFuncAttributeMaxDynamicSharedMemorySize, GSMEM);
    cudaFuncSetAttribute(hgemm_k<2>, cudaFuncAttributeMaxDynamicSharedMemorySize, GSMEM);
    cudaFuncSetAttribute(flash_k,    cudaFuncAttributeMaxDynamicSharedMemorySize, FSMEM);

    dim3 tb(32, 8);
    // launches 0..3: weight transposes; 4: embed; 5: first dense GEMM (ncu target)
    transpose_qkv_k<<<dim3(24, 24, 3 * Lz), tb>>>(Wq, Wk, Wv, wqkvT);
    transpose_f2h_k<<<dim3(24, 24, Lz), tb>>>(Wo, woT, Hz, Hz);
    transpose_f2h_k<<<dim3(96, 24, Lz), tb>>>(Wi, wiT, Hz, Iz);
    transpose_f2h_k<<<dim3(24, 96, Lz), tb>>>(Wo2, wo2T, Iz, Hz);
    embed_ln_k<<<Bz * Sz, 256>>>(ids, word, pos, type0, lneg, lneb, x, xb);

    const int M = Bz * Sz; // 8192
    for (int l = 0; l < Lz; l++) {
        // fused QKV projection: [8192,768] x [768,2304]^T -> qkv [8192][2304]
        {
            GP p{};
            p.A = xb;
            p.Bt = wqkvT + (size_t)l * 3 * Hz * Hz;
            p.bias = bq + l * Hz; p.bias1 = bk + l * Hz; p.bias2 = bv + l * Hz;
            p.outB = qkv; p.K = Hz; p.ldo = QLD;
            hgemm_k<0><<<dim3(QLD / 128, M / 128), 128, GSMEM>>>(p);
        }
        flash_k<<<dim3(Sz / 128, Bz * NHz), 256, FSMEM>>>(qkv, ctx);
        // O projection + bias + residual
        {
            GP p{};
            p.A = ctx; p.Bt = woT + (size_t)l * Hz * Hz;
            p.bias = bo + l * Hz; p.res = x; p.outF = tmp;
            p.K = Hz; p.ldo = Hz;
            hgemm_k<1><<<dim3(Hz / 128, M / 128), 128, GSMEM>>>(p);
        }
        ln_k<<<Bz * Sz, 256>>>(tmp, ln1g + l * Hz, ln1b + l * Hz, attn, attnb);
        // FFN1 + GELU
        {
            GP p{};
            p.A = attnb; p.Bt = wiT + (size_t)l * Hz * Iz;
            p.bias = bi + l * Iz; p.outB = hh;
            p.K = Hz; p.ldo = Iz;
            hgemm_k<2><<<dim3(Iz / 128, M / 128), 128, GSMEM>>>(p);
        }
        // FFN2 + bias + residual
        {
            GP p{};
            p.A = hh; p.Bt = wo2T + (size_t)l * Hz * Iz;
            p.bias = bo2 + l * Hz; p.res = attn; p.outF = tmp;
            p.K = Iz; p.ldo = Hz;
            hgemm_k<1><<<dim3(Hz / 128, M / 128), 128, GSMEM>>>(p);
        }
        float* outp = (l == Lz - 1) ? (float*)d_out : x;
        ln_k<<<Bz * Sz, 256>>>(tmp, ln2g + l * Hz, ln2b + l * Hz, outp, xb);
    }
}

// round 6
// speedup vs baseline: 1.6512x; 1.0965x over previous
#include <cuda_runtime.h>
#include <cuda_fp16.h>
#include <mma.h>
#include <cstdint>
#include <cstddef>

using namespace nvcuda;

#define Bz 16
#define Sz 512
#define Hz 768
#define Lz 12
#define NHz 12
#define Iz 3072
#define DHz 64
#define BSHz (Bz*Sz*Hz)
#define QLD 2304

// ---------------- scratch (device globals; no allocations allowed) ----------
__device__ __align__(16) float  g_x[BSHz];
__device__ __align__(16) float  g_tmp[BSHz];
__device__ __align__(16) float  g_attn[BSHz];
__device__ __align__(16) __half g_xb[BSHz];
__device__ __align__(16) __half g_attnb[BSHz];
__device__ __align__(16) __half g_qkv[3*BSHz];            // [8192][2304]
__device__ __align__(16) __half g_ctx[BSHz];
__device__ __align__(16) __half g_h[(size_t)Bz*Sz*Iz];
__device__ __align__(16) __half g_wqkvT[(size_t)Lz*3*Hz*Hz];   // [L][2304][768]
__device__ __align__(16) __half g_woT[(size_t)Lz*Hz*Hz];       // [L][768][768]
__device__ __align__(16) __half g_wiT[(size_t)Lz*Hz*Iz];       // [L][3072][768]
__device__ __align__(16) __half g_wo2T[(size_t)Lz*Hz*Iz];      // [L][768][3072]

// ---------------- cp.async helpers ------------------------------------------
__device__ __forceinline__ void cpa16(uint32_t d, const void* s) {
    asm volatile("cp.async.cg.shared.global [%0], [%1], 16;" :: "r"(d), "l"(s));
}
__device__ __forceinline__ void cpa_commit() { asm volatile("cp.async.commit_group;"); }
template<int N> __device__ __forceinline__ void cpa_wait() {
    asm volatile("cp.async.wait_group %0;" :: "n"(N));
}

// ---------------- weight transpose + fp32->fp16 ------------------------------
__global__ void transpose_f2h_k(const float* __restrict__ src, __half* __restrict__ dst,
                                int R, int C) {
    __shared__ float t[32][33];
    int bx = blockIdx.x * 32, by = blockIdx.y * 32;
    const float* s = src + (size_t)blockIdx.z * R * C;
    __half* d = dst + (size_t)blockIdx.z * R * C;
    int tx = threadIdx.x, ty = threadIdx.y;
    #pragma unroll
    for (int i = 0; i < 32; i += 8)
        t[ty + i][tx] = s[(size_t)(by + ty + i) * C + bx + tx];
    __syncthreads();
    #pragma unroll
    for (int i = 0; i < 32; i += 8)
        d[(size_t)(bx + ty + i) * R + by + tx] = __float2half_rn(t[tx][ty + i]);
}

// QKV: 3 sources -> [L][2304][768] fp16 (each slot transposed)
__global__ void transpose_qkv_k(const float* __restrict__ q, const float* __restrict__ k,
                                const float* __restrict__ v, __half* __restrict__ dst) {
    __shared__ float t[32][33];
    int z = blockIdx.z;
    int slot = z / Lz, l = z % Lz;
    const float* srcs = (slot == 0 ? q : (slot == 1 ? k : v)) + (size_t)l * Hz * Hz;
    __half* d = dst + ((size_t)l * 3 + slot) * Hz * Hz;
    int bx = blockIdx.x * 32, by = blockIdx.y * 32;
    int tx = threadIdx.x, ty = threadIdx.y;
    #pragma unroll
    for (int i = 0; i < 32; i += 8)
        t[ty + i][tx] = srcs[(size_t)(by + ty + i) * Hz + bx + tx];
    __syncthreads();
    #pragma unroll
    for (int i = 0; i < 32; i += 8)
        d[(size_t)(bx + ty + i) * Hz + by + tx] = __float2half_rn(t[tx][ty + i]);
}

// ---------------- block reductions ------------------------------------------
__device__ __forceinline__ float bsum256(float v, float* sm) {
    #pragma unroll
    for (int o = 16; o; o >>= 1) v += __shfl_xor_sync(0xFFFFFFFFu, v, o);
    int t = threadIdx.x;
    if ((t & 31) == 0) sm[t >> 5] = v;
    __syncthreads();
    float r = sm[0];
    #pragma unroll
    for (int i = 1; i < 8; i++) r += sm[i];
    __syncthreads();
    return r;
}

// ---------------- embedding + LN ---------------------------------------------
__global__ void embed_ln_k(const int* __restrict__ ids,
                           const float* __restrict__ we,
                           const float* __restrict__ pe,
                           const float* __restrict__ te,
                           const float* __restrict__ g,
                           const float* __restrict__ b,
                           float* __restrict__ dF,
                           __half* __restrict__ dB) {
    __shared__ float sm[8];
    int row = blockIdx.x;
    int s_ = row & (Sz - 1);
    int id = ids[row];
    int t = threadIdx.x;
    float v[3];
    #pragma unroll
    for (int i = 0; i < 3; i++) {
        int col = t + i * 256;
        v[i] = we[(size_t)id * Hz + col] + pe[(size_t)(s_ + 2) * Hz + col] + te[col];
    }
    float mean = bsum256(v[0] + v[1] + v[2], sm) * (1.0f / Hz);
    float d0 = v[0] - mean, d1 = v[1] - mean, d2 = v[2] - mean;
    float var = bsum256(d0*d0 + d1*d1 + d2*d2, sm) * (1.0f / Hz);
    float rs = rsqrtf(var + 1e-5f);
    size_t base = (size_t)row * Hz;
    #pragma unroll
    for (int i = 0; i < 3; i++) {
        int col = t + i * 256;
        float y = (v[i] - mean) * rs * g[col] + b[col];
        dF[base + col] = y;
        dB[base + col] = __float2half_rn(y);
    }
}

// ---------------- LayerNorm ---------------------------------------------------
__global__ void ln_k(const float* __restrict__ src,
                     const float* __restrict__ g,
                     const float* __restrict__ b,
                     float* __restrict__ dF,
                     __half* __restrict__ dB) {
    __shared__ float sm[8];
    size_t base = (size_t)blockIdx.x * Hz;
    int t = threadIdx.x;
    float v[3];
    #pragma unroll
    for (int i = 0; i < 3; i++) v[i] = src[base + t + i * 256];
    float mean = bsum256(v[0] + v[1] + v[2], sm) * (1.0f / Hz);
    float d0 = v[0] - mean, d1 = v[1] - mean, d2 = v[2] - mean;
    float var = bsum256(d0*d0 + d1*d1 + d2*d2, sm) * (1.0f / Hz);
    float rs = rsqrtf(var + 1e-5f);
    #pragma unroll
    for (int i = 0; i < 3; i++) {
        int col = t + i * 256;
        float y = (v[i] - mean) * rs * g[col] + b[col];
        if (dF) dF[base + col] = y;
        dB[base + col] = __float2half_rn(y);
    }
}

// ---------------- HMMA GEMM: 128x128 tile, 4 warps of 64x64, BK=64, 3-stage --
// A [M, K] fp16 K-major (lda=K). Bt [N, K] fp16 K-major (ldb=K).
// grid (N/128, M/128), 128 threads.
// EPI: 0 outB = half(acc + bias)   (bias1/bias2: QKV slot biases by column)
//      1 outF = acc + bias + res   2 outB = half(gelu(acc + bias))
struct GP {
    const __half* A;
    const __half* Bt;
    const float* bias;
    const float* bias1;
    const float* bias2;
    const float* res;
    float* outF;
    __half* outB;
    int K, ldo;
};

// stage s at s*36864: A 128x64 (pitch 72 halves = 144B) = 18432 B, B same at +18432
// epilogue reuses [0, 67584) as float 128x132
#define GSMEM 110592

template<int EPI>
__global__ void __launch_bounds__(128, 2) hgemm_k(GP p) {
    extern __shared__ __align__(16) char smraw[];
    const int tid = threadIdx.x;
    const int wid = tid >> 5;
    const int wm = wid >> 1, wn = wid & 1;     // 2x2 warp grid, 64x64 each
    const int m0 = blockIdx.y * 128, n0 = blockIdx.x * 128;

    const __half* Arow = p.A + (size_t)m0 * p.K;
    const __half* Brow = p.Bt + (size_t)n0 * p.K;
    const int K = p.K, KT = K >> 6;

    uint32_t sbase = (uint32_t)__cvta_generic_to_shared(smraw);

    // per stage: 128 rows x 8 16B-chunks per matrix; 128 threads -> 8 chunks each
    auto issue = [&](int kt, int st) {
        const __half* as = Arow + kt * 64;
        const __half* bs = Brow + kt * 64;
        const uint32_t sa = sbase + st * 36864;
        const uint32_t sb = sa + 18432;
        #pragma unroll
        for (int i = 0; i < 8; i++) {
            int g = tid + i * 128;
            int r = g >> 3, c = g & 7;
            cpa16(sa + r * 144 + c * 16, as + (size_t)r * K + c * 8);
            cpa16(sb + r * 144 + c * 16, bs + (size_t)r * K + c * 8);
        }
    };

    issue(0, 0); cpa_commit();
    issue(1, 1); cpa_commit();

    wmma::fragment<wmma::accumulator, 16, 16, 16, float> acc[4][4];
    #pragma unroll
    for (int i = 0; i < 4; i++)
        #pragma unroll
        for (int j = 0; j < 4; j++) wmma::fill_fragment(acc[i][j], 0.0f);

    for (int kt = 0; kt < KT; kt++) {
        cpa_wait<1>();
        __syncthreads();
        if (kt + 2 < KT) issue(kt + 2, (kt + 2) % 3);
        cpa_commit();

        const int st = kt % 3;
        const __half* sA = (const __half*)(smraw + st * 36864);
        const __half* sB = sA + 9216;   // 18432 bytes
        #pragma unroll
        for (int kk = 0; kk < 4; kk++) {
            wmma::fragment<wmma::matrix_a, 16, 16, 16, __half, wmma::row_major> af[4];
            #pragma unroll
            for (int i = 0; i < 4; i++)
                wmma::load_matrix_sync(af[i], sA + (wm * 64 + i * 16) * 72 + kk * 16, 72);
            wmma::fragment<wmma::matrix_b, 16, 16, 16, __half, wmma::col_major> bf[4];
            #pragma unroll
            for (int j = 0; j < 4; j++)
                wmma::load_matrix_sync(bf[j], sB + (wn * 64 + j * 16) * 72 + kk * 16, 72);
            #pragma unroll
            for (int i = 0; i < 4; i++)
                #pragma unroll
                for (int j = 0; j < 4; j++)
                    wmma::mma_sync(acc[i][j], af[i], bf[j], acc[i][j]);
        }
    }

    __syncthreads();
    float* epi = (float*)smraw;
    #pragma unroll
    for (int i = 0; i < 4; i++)
        #pragma unroll
        for (int j = 0; j < 4; j++)
            wmma::store_matrix_sync(epi + (wm * 64 + i * 16) * 132 + wn * 64 + j * 16,
                                    acc[i][j], 132, wmma::mem_row_major);
    __syncthreads();

    // epilogue: thread t handles row t (128 cols)
    {
        const float* ep = epi + tid * 132;
        const int gm = m0 + tid;
        if (EPI == 1) {
            float* orow = p.outF + (size_t)gm * p.ldo + n0;
            const float* rrow = p.res + (size_t)gm * p.ldo + n0;
            #pragma unroll 8
            for (int c = 0; c < 128; c += 4) {
                float4 r4 = *(const float4*)(rrow + c);
                float4 o;
                o.x = ep[c]     + p.bias[n0 + c]     + r4.x;
                o.y = ep[c + 1] + p.bias[n0 + c + 1] + r4.y;
                o.z = ep[c + 2] + p.bias[n0 + c + 2] + r4.z;
                o.w = ep[c + 3] + p.bias[n0 + c + 3] + r4.w;
                *(float4*)(orow + c) = o;
            }
        } else {
            __half* orow = p.outB + (size_t)gm * p.ldo + n0;
            #pragma unroll 4
            for (int c0 = 0; c0 < 128; c0 += 8) {
                float f[8];
                #pragma unroll
                for (int j = 0; j < 8; j++) {
                    int n = n0 + c0 + j;
                    float bv;
                    if (EPI == 0 && p.bias1) {
                        const float* bp = n < 768 ? p.bias : (n < 1536 ? p.bias1 : p.bias2);
                        bv = bp[n & 767];
                    } else {
                        bv = p.bias[n];
                    }
                    f[j] = ep[c0 + j] + bv;
                }
                if (EPI == 2) {
                    #pragma unroll
                    for (int j = 0; j < 8; j++)
                        f[j] = 0.5f * f[j] * (1.0f + erff(f[j] * 0.70710678118654752f));
                }
                __half2 h[4];
                #pragma unroll
                for (int j = 0; j < 4; j++) h[j] = __floats2half2_rn(f[2*j], f[2*j+1]);
                *(uint4*)(orow + c0) = *(uint4*)h;
            }
        }
    }
}

// ---------------- fused flash attention (wmma) -------------------------------
// qkv buffer layout: [8192 rows][2304] halves; Q cols [0,768), K [768,1536), V [1536,2304)
#define FSMEM 108032

__global__ void __launch_bounds__(256, 2) flash_k(const __half* __restrict__ qkv,
                                                  __half* __restrict__ ctx) {
    extern __shared__ __align__(16) char sm[];
    __half* sQ = (__half*)sm;
    __half* sK = (__half*)(sm + 18432);
    __half* sV = (__half*)(sm + 27648);
    float*  sS = (float*)(sm + 36864);
    __half* sP = (__half*)(sm + 36864);
    float*  sO = (float*)(sm + 71680);
    float*  sMm = (float*)(sm + 106496);
    float*  sF = sMm + 128;
    float*  sL = sF + 128;

    const int tid = threadIdx.x;
    const int wid = tid >> 5;
    const int wm = wid >> 1, wn = wid & 1;
    const int qt = blockIdx.x;
    const int z = blockIdx.y;
    const int b = z / NHz, h = z % NHz;

    const __half* Qp = qkv + (size_t)(b * Sz) * QLD + h * DHz;
    const __half* Kp = Qp + 768;
    const __half* Vp = Qp + 1536;

    #pragma unroll
    for (int s = 0; s < 4; s++) {
        int ch = tid + s * 256;
        int r = ch >> 3, c = (ch & 7) << 3;
        *(uint4*)(sQ + r * 72 + c) = *(const uint4*)(Qp + (size_t)(qt * 128 + r) * QLD + c);
    }
    #pragma unroll
    for (int s = 0; s < 32; s++) {
        int e = tid + s * 256;
        sO[(e >> 6) * 68 + (e & 63)] = 0.0f;
    }
    if (tid < 128) { sMm[tid] = -1e30f; sL[tid] = 0.0f; }

    const int r = tid >> 1, hf = tid & 1;

    for (int kt = 0; kt < 8; kt++) {
        #pragma unroll
        for (int s = 0; s < 2; s++) {
            int ch = tid + s * 256;
            int rr = ch >> 3, c = (ch & 7) << 3;
            size_t go = (size_t)(kt * 64 + rr) * QLD + c;
            *(uint4*)(sK + rr * 72 + c) = *(const uint4*)(Kp + go);
            *(uint4*)(sV + rr * 72 + c) = *(const uint4*)(Vp + go);
        }
        __syncthreads();

        {
            wmma::fragment<wmma::accumulator, 16, 16, 16, float> sacc[2][2];
            #pragma unroll
            for (int i = 0; i < 2; i++)
                #pragma unroll
                for (int j = 0; j < 2; j++) wmma::fill_fragment(sacc[i][j], 0.0f);
            #pragma unroll
            for (int k = 0; k < 4; k++) {
                wmma::fragment<wmma::matrix_a, 16, 16, 16, __half, wmma::row_major> a[2];
                wmma::fragment<wmma::matrix_b, 16, 16, 16, __half, wmma::col_major> bb[2];
                #pragma unroll
                for (int i = 0; i < 2; i++)
                    wmma::load_matrix_sync(a[i], sQ + (wm * 32 + i * 16) * 72 + k * 16, 72);
                #pragma unroll
                for (int j = 0; j < 2; j++)
                    wmma::load_matrix_sync(bb[j], sK + (wn * 32 + j * 16) * 72 + k * 16, 72);
                #pragma unroll
                for (int i = 0; i < 2; i++)
                    #pragma unroll
                    for (int j = 0; j < 2; j++)
                        wmma::mma_sync(sacc[i][j], a[i], bb[j], sacc[i][j]);
            }
            #pragma unroll
            for (int i = 0; i < 2; i++)
                #pragma unroll
                for (int j = 0; j < 2; j++)
                    wmma::store_matrix_sync(sS + (wm * 32 + i * 16) * 68 + wn * 32 + j * 16,
                                            sacc[i][j], 68, wmma::mem_row_major);
        }
        __syncthreads();

        {
            float pv[32];
            float mold = sMm[r];
            float tmax = -1e30f;
            #pragma unroll
            for (int c = 0; c < 32; c++) {
                float s = sS[r * 68 + hf * 32 + c] * 0.125f;
                pv[c] = s;
                tmax = fmaxf(tmax, s);
            }
            tmax = fmaxf(tmax, __shfl_xor_sync(0xFFFFFFFFu, tmax, 1));
            float mnew = fmaxf(mold, tmax);
            float lsum = 0.0f;
            #pragma unroll
            for (int c = 0; c < 32; c++) {
                pv[c] = __expf(pv[c] - mnew);
                lsum += pv[c];
            }
            lsum += __shfl_xor_sync(0xFFFFFFFFu, lsum, 1);
            __syncwarp();
            #pragma unroll
            for (int c = 0; c < 32; c++)
                sP[r * 136 + hf * 32 + c] = __float2half_rn(pv[c]);
            if (!hf) {
                float f = __expf(mold - mnew);
                sF[r] = f;
                sMm[r] = mnew;
                sL[r] = sL[r] * f + lsum;
            }
        }
        __syncthreads();

        {
            wmma::fragment<wmma::accumulator, 16, 16, 16, float> oacc[2][2];
            #pragma unroll
            for (int i = 0; i < 2; i++)
                #pragma unroll
                for (int j = 0; j < 2; j++) wmma::fill_fragment(oacc[i][j], 0.0f);
            #pragma unroll
            for (int k = 0; k < 4; k++) {
                wmma::fragment<wmma::matrix_a, 16, 16, 16, __half, wmma::row_major> a[2];
                wmma::fragment<wmma::matrix_b, 16, 16, 16, __half, wmma::row_major> bb[2];
                #pragma unroll
                for (int i = 0; i < 2; i++)
                    wmma::load_matrix_sync(a[i], sP + (wm * 32 + i * 16) * 136 + k * 16, 136);
                #pragma unroll
                for (int j = 0; j < 2; j++)
                    wmma::load_matrix_sync(bb[j], sV + (k * 16) * 72 + wn * 32 + j * 16, 72);
                #pragma unroll
                for (int i = 0; i < 2; i++)
                    #pragma unroll
                    for (int j = 0; j < 2; j++)
                        wmma::mma_sync(oacc[i][j], a[i], bb[j], oacc[i][j]);
            }
            __syncthreads();
            #pragma unroll
            for (int i = 0; i < 2; i++)
                #pragma unroll
                for (int j = 0; j < 2; j++)
                    wmma::store_matrix_sync(sS + (wm * 32 + i * 16) * 68 + wn * 32 + j * 16,
                                            oacc[i][j], 68, wmma::mem_row_major);
        }
        __syncthreads();

        {
            float f = sF[r];
            #pragma unroll
            for (int c = 0; c < 32; c++) {
                int idx = r * 68 + hf * 32 + c;
                sO[idx] = sO[idx] * f + sS[idx];
            }
        }
        __syncthreads();
    }

    {
        float inv = 1.0f / sL[r];
        __half* dst = ctx + ((size_t)(b * Sz) + qt * 128 + r) * Hz + h * DHz + hf * 32;
        #pragma unroll
        for (int c = 0; c < 32; c++)
            dst[c] = __float2half_rn(sO[r * 68 + hf * 32 + c] * inv);
    }
}

// ---------------- host orchestration ----------------------------------------
extern "C" void kernel_launch(void* const* d_in, const int* in_sizes, int n_in,
                              void* d_out, int out_size) {
    const int*   ids   = (const int*)d_in[0];
    const float* word  = (const float*)d_in[1];
    const float* pos   = (const float*)d_in[2];
    const float* type0 = (const float*)d_in[3];
    const float* lneg  = (const float*)d_in[4];
    const float* lneb  = (const float*)d_in[5];
    const float* Wq    = (const float*)d_in[6];
    const float* bq    = (const float*)d_in[7];
    const float* Wk    = (const float*)d_in[8];
    const float* bk    = (const float*)d_in[9];
    const float* Wv    = (const float*)d_in[10];
    const float* bv    = (const float*)d_in[11];
    const float* Wo    = (const float*)d_in[12];
    const float* bo    = (const float*)d_in[13];
    const float* ln1g  = (const float*)d_in[14];
    const float* ln1b  = (const float*)d_in[15];
    const float* Wi    = (const float*)d_in[16];
    const float* bi    = (const float*)d_in[17];
    const float* Wo2   = (const float*)d_in[18];
    const float* bo2   = (const float*)d_in[19];
    const float* ln2g  = (const float*)d_in[20];
    const float* ln2b  = (const float*)d_in[21];

    float *x, *tmp, *attn;
    __half *xb, *attnb, *qkv, *ctx, *hh, *wqkvT, *woT, *wiT, *wo2T;
    cudaGetSymbolAddress((void**)&x,     g_x);
    cudaGetSymbolAddress((void**)&tmp,   g_tmp);
    cudaGetSymbolAddress((void**)&attn,  g_attn);
    cudaGetSymbolAddress((void**)&xb,    g_xb);
    cudaGetSymbolAddress((void**)&attnb, g_attnb);
    cudaGetSymbolAddress((void**)&qkv,   g_qkv);
    cudaGetSymbolAddress((void**)&ctx,   g_ctx);
    cudaGetSymbolAddress((void**)&hh,    g_h);
    cudaGetSymbolAddress((void**)&wqkvT, g_wqkvT);
    cudaGetSymbolAddress((void**)&woT,   g_woT);
    cudaGetSymbolAddress((void**)&wiT,   g_wiT);
    cudaGetSymbolAddress((void**)&wo2T,  g_wo2T);

    cudaFuncSetAttribute(hgemm_k<0>, cudaFuncAttributeMaxDynamicSharedMemorySize, GSMEM);
    cudaFuncSetAttribute(hgemm_k<1>, cudaFuncAttributeMaxDynamicSharedMemorySize, GSMEM);
    cudaFuncSetAttribute(hgemm_k<2>, cudaFuncAttributeMaxDynamicSharedMemorySize, GSMEM);
    cudaFuncSetAttribute(flash_k,    cudaFuncAttributeMaxDynamicSharedMemorySize, FSMEM);

    dim3 tb(32, 8);
    // launches 0..3: weight transposes; 4: embed; 5: first dense GEMM (ncu target)
    transpose_qkv_k<<<dim3(24, 24, 3 * Lz), tb>>>(Wq, Wk, Wv, wqkvT);
    transpose_f2h_k<<<dim3(24, 24, Lz), tb>>>(Wo, woT, Hz, Hz);
    transpose_f2h_k<<<dim3(96, 24, Lz), tb>>>(Wi, wiT, Hz, Iz);
    transpose_f2h_k<<<dim3(24, 96, Lz), tb>>>(Wo2, wo2T, Iz, Hz);
    embed_ln_k<<<Bz * Sz, 256>>>(ids, word, pos, type0, lneg, lneb, x, xb);

    const int M = Bz * Sz; // 8192
    for (int l = 0; l < Lz; l++) {
        // fused QKV projection: [8192,768] x [768,2304]^T -> qkv [8192][2304]
        {
            GP p{};
            p.A = xb;
            p.Bt = wqkvT + (size_t)l * 3 * Hz * Hz;
            p.bias = bq + l * Hz; p.bias1 = bk + l * Hz; p.bias2 = bv + l * Hz;
            p.outB = qkv; p.K = Hz; p.ldo = QLD;
            hgemm_k<0><<<dim3(QLD / 128, M / 128), 128, GSMEM>>>(p);
        }
        flash_k<<<dim3(Sz / 128, Bz * NHz), 256, FSMEM>>>(qkv, ctx);
        // O projection + bias + residual
        {
            GP p{};
            p.A = ctx; p.Bt = woT + (size_t)l * Hz * Hz;
            p.bias = bo + l * Hz; p.res = x; p.outF = tmp;
            p.K = Hz; p.ldo = Hz;
            hgemm_k<1><<<dim3(Hz / 128, M / 128), 128, GSMEM>>>(p);
        }
        ln_k<<<Bz * Sz, 256>>>(tmp, ln1g + l * Hz, ln1b + l * Hz, attn, attnb);
        // FFN1 + GELU
        {
            GP p{};
            p.A = attnb; p.Bt = wiT + (size_t)l * Hz * Iz;
            p.bias = bi + l * Iz; p.outB = hh;
            p.K = Hz; p.ldo = Iz;
            hgemm_k<2><<<dim3(Iz / 128, M / 128), 128, GSMEM>>>(p);
        }
        // FFN2 + bias + residual
        {
            GP p{};
            p.A = hh; p.Bt = wo2T + (size_t)l * Hz * Iz;
            p.bias = bo2 + l * Hz; p.res = attn; p.outF = tmp;
            p.K = Iz; p.ldo = Hz;
            hgemm_k<1><<<dim3(Hz / 128, M / 128), 128, GSMEM>>>(p);
        }
        float* outp = (l == Lz - 1) ? (float*)d_out : x;
        ln_k<<<Bz * Sz, 256>>>(tmp, ln2g + l * Hz, ln2b + l * Hz, outp, xb);
    }
}